// round 2
// baseline (speedup 1.0000x reference)
#include <cuda_runtime.h>
#include <cstdint>

// out[b] = (X X^T) X  ==  X (X^T X)   (associativity: G = X^T X is only 128x128)
// B=4, T=4096, D=128 fp32.
// 3 launches: (1) partial Gram per 128-row chunk, (2) reduce partials, (3) out = X*G.

#define NB     4
#define TT     4096
#define DD     128
#define SPLITS 32
#define CHUNK  128

// scratch: deterministic device globals (no runtime allocation)
__device__ float g_partial[NB * SPLITS * DD * DD];  // 8 MB
__device__ float g_G[NB * DD * DD];                 // 256 KB

// ---------------------------------------------------------------------------
// Kernel 1: P[b,s] = Xc^T * Xc   for chunk Xc = x[b, s*128:(s+1)*128, :]
// 256 threads, 16x16 thread grid, 8x8 accumulator per thread.
// Both operands are read from the SAME smem row (contiguous) -> conflict-free.
// ---------------------------------------------------------------------------
__global__ void __launch_bounds__(256, 1)
syrk_kernel(const float* __restrict__ x)
{
    extern __shared__ float As[];  // [128][128]
    const int s = blockIdx.x, b = blockIdx.y;
    const int tid = threadIdx.x;

    const float4* xg = reinterpret_cast<const float4*>(
        x + ((size_t)b * TT + (size_t)s * CHUNK) * DD);
    float4* Asv = reinterpret_cast<float4*>(As);
#pragma unroll
    for (int j = 0; j < 16; j++)
        Asv[tid + j * 256] = xg[tid + j * 256];
    __syncthreads();

    const int ty = tid >> 4;        // 0..15 -> output rows d1 = ty*8..
    const int tx = tid & 15;        // 0..15 -> output cols d2 = tx*8..

    float acc[8][8];
#pragma unroll
    for (int i = 0; i < 8; i++)
#pragma unroll
        for (int j = 0; j < 8; j++) acc[i][j] = 0.0f;

#pragma unroll 4
    for (int k = 0; k < 128; k++) {
        const float* r = As + k * 128;
        float4 a0 = *reinterpret_cast<const float4*>(r + ty * 8);
        float4 a1 = *reinterpret_cast<const float4*>(r + ty * 8 + 4);
        float4 b0 = *reinterpret_cast<const float4*>(r + tx * 8);
        float4 b1 = *reinterpret_cast<const float4*>(r + tx * 8 + 4);
        float a[8] = {a0.x, a0.y, a0.z, a0.w, a1.x, a1.y, a1.z, a1.w};
        float bb[8] = {b0.x, b0.y, b0.z, b0.w, b1.x, b1.y, b1.z, b1.w};
#pragma unroll
        for (int i = 0; i < 8; i++)
#pragma unroll
            for (int j = 0; j < 8; j++)
                acc[i][j] = fmaf(a[i], bb[j], acc[i][j]);
    }

    float* outp = g_partial + (size_t)(b * SPLITS + s) * DD * DD;
#pragma unroll
    for (int i = 0; i < 8; i++) {
        float* row = outp + (ty * 8 + i) * DD + tx * 8;
        *reinterpret_cast<float4*>(row)     = make_float4(acc[i][0], acc[i][1], acc[i][2], acc[i][3]);
        *reinterpret_cast<float4*>(row + 4) = make_float4(acc[i][4], acc[i][5], acc[i][6], acc[i][7]);
    }
}

// ---------------------------------------------------------------------------
// Kernel 2: G[b] = sum_s P[b,s]   (16384 float4 outputs, 32-way sum each)
// ---------------------------------------------------------------------------
__global__ void __launch_bounds__(256, 1)
reduce_kernel()
{
    const int idx = blockIdx.x * 256 + threadIdx.x;  // 0..16383 float4 index
    const int b = idx >> 12;                         // 4096 float4 per batch
    const int e = idx & 4095;

    const float4* base = reinterpret_cast<const float4*>(g_partial)
                       + (size_t)b * SPLITS * 4096 + e;
    float4 acc = make_float4(0.f, 0.f, 0.f, 0.f);
#pragma unroll
    for (int s = 0; s < SPLITS; s++) {
        float4 v = base[(size_t)s * 4096];
        acc.x += v.x; acc.y += v.y; acc.z += v.z; acc.w += v.w;
    }
    reinterpret_cast<float4*>(g_G)[idx] = acc;
}

// ---------------------------------------------------------------------------
// Kernel 3: out_chunk = Xc * G[b].  X is transposed into padded smem so the
// A-operand (column of Xc per k) becomes a contiguous row read.
// ---------------------------------------------------------------------------
#define XT_PITCH 132

__global__ void __launch_bounds__(256, 1)
gemm_kernel(const float* __restrict__ x, float* __restrict__ out)
{
    extern __shared__ float sm[];
    float* Gs = sm;                  // [128][128]
    float* Xt = sm + DD * DD;        // [128][132] transposed chunk

    const int s = blockIdx.x, b = blockIdx.y;
    const int tid = threadIdx.x;

    // G -> smem (straight float4 copy)
    {
        const float4* gg = reinterpret_cast<const float4*>(g_G + (size_t)b * DD * DD);
        float4* gs = reinterpret_cast<float4*>(Gs);
#pragma unroll
        for (int j = 0; j < 16; j++)
            gs[tid + j * 256] = gg[tid + j * 256];
    }
    // X chunk -> transposed smem
    {
        const float4* xg = reinterpret_cast<const float4*>(
            x + ((size_t)b * TT + (size_t)s * CHUNK) * DD);
#pragma unroll
        for (int j = 0; j < 16; j++) {
            int idx = tid + j * 256;       // float4 index in [128 rows][32 f4]
            int t  = idx >> 5;             // row (t within chunk)
            int kq = idx & 31;             // float4 column
            float4 v = xg[idx];
            Xt[(kq * 4 + 0) * XT_PITCH + t] = v.x;
            Xt[(kq * 4 + 1) * XT_PITCH + t] = v.y;
            Xt[(kq * 4 + 2) * XT_PITCH + t] = v.z;
            Xt[(kq * 4 + 3) * XT_PITCH + t] = v.w;
        }
    }
    __syncthreads();

    const int ty = tid >> 4;  // output rows t = ty*8..
    const int tx = tid & 15;  // output cols d = tx*8..

    float acc[8][8];
#pragma unroll
    for (int i = 0; i < 8; i++)
#pragma unroll
        for (int j = 0; j < 8; j++) acc[i][j] = 0.0f;

#pragma unroll 4
    for (int k = 0; k < 128; k++) {
        const float* ar = Xt + k * XT_PITCH;   // row k of X^T: contiguous in t
        const float* br = Gs + k * 128;
        float4 a0 = *reinterpret_cast<const float4*>(ar + ty * 8);
        float4 a1 = *reinterpret_cast<const float4*>(ar + ty * 8 + 4);
        float4 b0 = *reinterpret_cast<const float4*>(br + tx * 8);
        float4 b1 = *reinterpret_cast<const float4*>(br + tx * 8 + 4);
        float a[8] = {a0.x, a0.y, a0.z, a0.w, a1.x, a1.y, a1.z, a1.w};
        float bb[8] = {b0.x, b0.y, b0.z, b0.w, b1.x, b1.y, b1.z, b1.w};
#pragma unroll
        for (int i = 0; i < 8; i++)
#pragma unroll
            for (int j = 0; j < 8; j++)
                acc[i][j] = fmaf(a[i], bb[j], acc[i][j]);
    }

    float* ob = out + ((size_t)b * TT + (size_t)s * CHUNK) * DD;
#pragma unroll
    for (int i = 0; i < 8; i++) {
        float* row = ob + (ty * 8 + i) * DD + tx * 8;
        *reinterpret_cast<float4*>(row)     = make_float4(acc[i][0], acc[i][1], acc[i][2], acc[i][3]);
        *reinterpret_cast<float4*>(row + 4) = make_float4(acc[i][4], acc[i][5], acc[i][6], acc[i][7]);
    }
}

// ---------------------------------------------------------------------------

extern "C" void kernel_launch(void* const* d_in, const int* in_sizes, int n_in,
                              void* d_out, int out_size)
{
    (void)in_sizes; (void)n_in; (void)out_size;
    const float* x = (const float*)d_in[0];
    float* out = (float*)d_out;

    const int smemA = DD * DD * 4;                       // 64 KB
    const int smemC = DD * DD * 4 + DD * XT_PITCH * 4;   // 64 KB + 66 KB

    cudaFuncSetAttribute(syrk_kernel, cudaFuncAttributeMaxDynamicSharedMemorySize, smemA);
    cudaFuncSetAttribute(gemm_kernel, cudaFuncAttributeMaxDynamicSharedMemorySize, smemC);

    syrk_kernel<<<dim3(SPLITS, NB), 256, smemA>>>(x);
    reduce_kernel<<<64, 256>>>();
    gemm_kernel<<<dim3(SPLITS, NB), 256, smemC>>>(x, out);
}

// round 3
// speedup vs baseline: 1.3950x; 1.3950x over previous
#include <cuda_runtime.h>
#include <cstdint>

// out[b] = (X X^T) X == X (X^T X);  G = X^T X is 128x128 per batch.
// Tensor-core path: mma.sync.m16n8k8 tf32 with 3-term hi/lo error compensation
// (A*B ~= Ahi*Bhi + Ahi*Blo + Alo*Bhi, residual ~2^-22).
// 3 launches: (1) partial Gram per 128-row chunk (tensor), (2) reduce, (3) out = X*G (tensor).

#define NB     4
#define TT     4096
#define DD     128
#define SPLITS 32
#define CHUNK  128
#define P1     132   // pitch (floats) for 128-wide smem tiles: 132 % 32 == 4 -> frag reads conflict-free
#define PX     68    // pitch for 64-wide X half tiles: 68 % 32 == 4

__device__ float g_partial[NB * SPLITS * DD * DD];  // 8 MB
__device__ float g_G[NB * DD * DD];                 // 256 KB

__device__ __forceinline__ uint32_t f2tf32(float v) {
    uint32_t u;
    asm("cvt.rna.tf32.f32 %0, %1;" : "=r"(u) : "f"(v));
    return u;
}

__device__ __forceinline__ void mma_tf32(float* d, const uint32_t* a, const uint32_t* b) {
    asm volatile(
        "mma.sync.aligned.m16n8k8.row.col.f32.tf32.tf32.f32 "
        "{%0,%1,%2,%3}, {%4,%5,%6,%7}, {%8,%9}, {%0,%1,%2,%3};"
        : "+f"(d[0]), "+f"(d[1]), "+f"(d[2]), "+f"(d[3])
        : "r"(a[0]), "r"(a[1]), "r"(a[2]), "r"(a[3]), "r"(b[0]), "r"(b[1]));
}

// ---------------------------------------------------------------------------
// Kernel 1: P[b,s] = Xc^T * Xc, Xc = x[b, s*128:(s+1)*128, :]   (tensor cores)
// smem: XT hi/lo, layout [d][t] pitch 132. 8 warps: 4(m) x 2(n), each 32m x 64n.
// ---------------------------------------------------------------------------
__global__ void __launch_bounds__(256, 1)
syrk_kernel(const float* __restrict__ x)
{
    extern __shared__ float sm[];
    float* Hi = sm;               // [128][132]
    float* Lo = sm + DD * P1;     // [128][132]

    const int s = blockIdx.x, b = blockIdx.y;
    const int tid = threadIdx.x, lane = tid & 31, w = tid >> 5;

    const float4* xg = reinterpret_cast<const float4*>(
        x + ((size_t)b * TT + (size_t)s * CHUNK) * DD);

    // Transposed fill: warp covers 16 t-rows x 2 kq-chunks per iter.
    // Write banks: 16*(lane&1) + (lane>>1) -> all 32 distinct (pitch 132).
    {
        const int t = w * 16 + (lane >> 1);
#pragma unroll
        for (int j = 0; j < 16; j++) {
            const int kq = (lane & 1) + 2 * j;
            float4 v = xg[t * 32 + kq];
            float vv[4] = {v.x, v.y, v.z, v.w};
#pragma unroll
            for (int i = 0; i < 4; i++) {
                float hi = __uint_as_float(f2tf32(vv[i]));
                float lo = __uint_as_float(f2tf32(vv[i] - hi));
                Hi[(4 * kq + i) * P1 + t] = hi;
                Lo[(4 * kq + i) * P1 + t] = lo;
            }
        }
    }
    __syncthreads();

    const int m0 = (w >> 1) * 32;
    const int n0 = (w & 1) * 64;
    const int gr = lane >> 2;   // group row 0..7
    const int gc = lane & 3;    // group col 0..3

    float acc[2][8][4];
#pragma unroll
    for (int mt = 0; mt < 2; mt++)
#pragma unroll
        for (int nt = 0; nt < 8; nt++)
#pragma unroll
            for (int q = 0; q < 4; q++) acc[mt][nt][q] = 0.0f;

    const uint32_t* HiU = reinterpret_cast<const uint32_t*>(Hi);
    const uint32_t* LoU = reinterpret_cast<const uint32_t*>(Lo);

#pragma unroll 1
    for (int k0 = 0; k0 < 128; k0 += 8) {
        uint32_t ah[2][4], al[2][4];
#pragma unroll
        for (int mt = 0; mt < 2; mt++) {
            const int r = (m0 + mt * 16 + gr) * P1 + k0 + gc;
            ah[mt][0] = HiU[r];             al[mt][0] = LoU[r];
            ah[mt][1] = HiU[r + 8 * P1];    al[mt][1] = LoU[r + 8 * P1];
            ah[mt][2] = HiU[r + 4];         al[mt][2] = LoU[r + 4];
            ah[mt][3] = HiU[r + 8 * P1 + 4];al[mt][3] = LoU[r + 8 * P1 + 4];
        }
#pragma unroll
        for (int nt = 0; nt < 8; nt++) {
            const int rn = (n0 + nt * 8 + gr) * P1 + k0 + gc;
            uint32_t bh[2] = {HiU[rn], HiU[rn + 4]};
            uint32_t bl[2] = {LoU[rn], LoU[rn + 4]};
#pragma unroll
            for (int mt = 0; mt < 2; mt++) {
                mma_tf32(acc[mt][nt], ah[mt], bh);
                mma_tf32(acc[mt][nt], ah[mt], bl);
                mma_tf32(acc[mt][nt], al[mt], bh);
            }
        }
    }

    float* outp = g_partial + (size_t)(b * SPLITS + s) * DD * DD;
#pragma unroll
    for (int mt = 0; mt < 2; mt++)
#pragma unroll
        for (int nt = 0; nt < 8; nt++) {
            const int row = m0 + mt * 16 + gr;
            const int col = n0 + nt * 8 + 2 * gc;
            *reinterpret_cast<float2*>(outp + row * DD + col) =
                make_float2(acc[mt][nt][0], acc[mt][nt][1]);
            *reinterpret_cast<float2*>(outp + (row + 8) * DD + col) =
                make_float2(acc[mt][nt][2], acc[mt][nt][3]);
        }
}

// ---------------------------------------------------------------------------
// Kernel 2: G[b] = sum_s P[b,s]
// ---------------------------------------------------------------------------
__global__ void __launch_bounds__(256, 1)
reduce_kernel()
{
    const int idx = blockIdx.x * 256 + threadIdx.x;  // float4 index
    const int b = idx >> 12;
    const int e = idx & 4095;

    const float4* base = reinterpret_cast<const float4*>(g_partial)
                       + (size_t)b * SPLITS * 4096 + e;
    float4 acc = make_float4(0.f, 0.f, 0.f, 0.f);
#pragma unroll
    for (int s = 0; s < SPLITS; s++) {
        float4 v = base[(size_t)s * 4096];
        acc.x += v.x; acc.y += v.y; acc.z += v.z; acc.w += v.w;
    }
    reinterpret_cast<float4*>(g_G)[idx] = acc;
}

// ---------------------------------------------------------------------------
// Kernel 3: out_chunk = Xc * G[b]   (tensor cores)
// A = Xc row-major (no transpose); B-frags read Gs[n][k] (G symmetric).
// smem: Ghi/Glo full [128][132], Xhi/Xlo half-k [128][68] (staged twice).
// ---------------------------------------------------------------------------
__global__ void __launch_bounds__(256, 1)
gemm_kernel(const float* __restrict__ x, float* __restrict__ out)
{
    extern __shared__ float sm[];
    float* Ghi = sm;                    // [128][132]
    float* Glo = sm + DD * P1;          // [128][132]
    float* Xhi = sm + 2 * DD * P1;      // [128][68]
    float* Xlo = sm + 2 * DD * P1 + DD * PX;

    const int s = blockIdx.x, b = blockIdx.y;
    const int tid = threadIdx.x, lane = tid & 31, w = tid >> 5;

    const float4* xg = reinterpret_cast<const float4*>(
        x + ((size_t)b * TT + (size_t)s * CHUNK) * DD);
    const float4* gg = reinterpret_cast<const float4*>(g_G + (size_t)b * DD * DD);

    // Fill G hi/lo (row-major copy, pitch 132)
#pragma unroll
    for (int j = 0; j < 16; j++) {
        const int idx = tid + j * 256;
        const int n = idx >> 5, kq = idx & 31;
        float4 v = gg[idx];
        float4 h, l;
        h.x = __uint_as_float(f2tf32(v.x)); l.x = __uint_as_float(f2tf32(v.x - h.x));
        h.y = __uint_as_float(f2tf32(v.y)); l.y = __uint_as_float(f2tf32(v.y - h.y));
        h.z = __uint_as_float(f2tf32(v.z)); l.z = __uint_as_float(f2tf32(v.z - h.z));
        h.w = __uint_as_float(f2tf32(v.w)); l.w = __uint_as_float(f2tf32(v.w - h.w));
        *reinterpret_cast<float4*>(Ghi + n * P1 + 4 * kq) = h;
        *reinterpret_cast<float4*>(Glo + n * P1 + 4 * kq) = l;
    }
    // Fill X half 0
#pragma unroll
    for (int j = 0; j < 8; j++) {
        const int idx = tid + j * 256;
        const int t = idx >> 4, kq = idx & 15;
        float4 v = xg[t * 32 + kq];
        float4 h, l;
        h.x = __uint_as_float(f2tf32(v.x)); l.x = __uint_as_float(f2tf32(v.x - h.x));
        h.y = __uint_as_float(f2tf32(v.y)); l.y = __uint_as_float(f2tf32(v.y - h.y));
        h.z = __uint_as_float(f2tf32(v.z)); l.z = __uint_as_float(f2tf32(v.z - h.z));
        h.w = __uint_as_float(f2tf32(v.w)); l.w = __uint_as_float(f2tf32(v.w - h.w));
        *reinterpret_cast<float4*>(Xhi + t * PX + 4 * kq) = h;
        *reinterpret_cast<float4*>(Xlo + t * PX + 4 * kq) = l;
    }
    __syncthreads();

    const int m0 = (w >> 1) * 32;
    const int n0 = (w & 1) * 64;
    const int gr = lane >> 2;
    const int gc = lane & 3;

    float acc[2][8][4];
#pragma unroll
    for (int mt = 0; mt < 2; mt++)
#pragma unroll
        for (int nt = 0; nt < 8; nt++)
#pragma unroll
            for (int q = 0; q < 4; q++) acc[mt][nt][q] = 0.0f;

    const uint32_t* GhU = reinterpret_cast<const uint32_t*>(Ghi);
    const uint32_t* GlU = reinterpret_cast<const uint32_t*>(Glo);
    const uint32_t* XhU = reinterpret_cast<const uint32_t*>(Xhi);
    const uint32_t* XlU = reinterpret_cast<const uint32_t*>(Xlo);

#pragma unroll 1
    for (int h = 0; h < 2; h++) {
#pragma unroll 1
        for (int k0 = 0; k0 < 64; k0 += 8) {
            uint32_t ah[2][4], al[2][4];
#pragma unroll
            for (int mt = 0; mt < 2; mt++) {
                const int r = (m0 + mt * 16 + gr) * PX + k0 + gc;
                ah[mt][0] = XhU[r];             al[mt][0] = XlU[r];
                ah[mt][1] = XhU[r + 8 * PX];    al[mt][1] = XlU[r + 8 * PX];
                ah[mt][2] = XhU[r + 4];         al[mt][2] = XlU[r + 4];
                ah[mt][3] = XhU[r + 8 * PX + 4];al[mt][3] = XlU[r + 8 * PX + 4];
            }
            const int kg = h * 64 + k0;  // global k into G
#pragma unroll
            for (int nt = 0; nt < 8; nt++) {
                const int rn = (n0 + nt * 8 + gr) * P1 + kg + gc;
                uint32_t bh[2] = {GhU[rn], GhU[rn + 4]};
                uint32_t bl[2] = {GlU[rn], GlU[rn + 4]};
#pragma unroll
                for (int mt = 0; mt < 2; mt++) {
                    mma_tf32(acc[mt][nt], ah[mt], bh);
                    mma_tf32(acc[mt][nt], ah[mt], bl);
                    mma_tf32(acc[mt][nt], al[mt], bh);
                }
            }
        }
        if (h == 0) {
            __syncthreads();
            // Fill X half 1 (overwrite half buffer)
#pragma unroll
            for (int j = 0; j < 8; j++) {
                const int idx = tid + j * 256;
                const int t = idx >> 4, kq = idx & 15;
                float4 v = xg[t * 32 + 16 + kq];
                float4 hh, ll;
                hh.x = __uint_as_float(f2tf32(v.x)); ll.x = __uint_as_float(f2tf32(v.x - hh.x));
                hh.y = __uint_as_float(f2tf32(v.y)); ll.y = __uint_as_float(f2tf32(v.y - hh.y));
                hh.z = __uint_as_float(f2tf32(v.z)); ll.z = __uint_as_float(f2tf32(v.z - hh.z));
                hh.w = __uint_as_float(f2tf32(v.w)); ll.w = __uint_as_float(f2tf32(v.w - hh.w));
                *reinterpret_cast<float4*>(Xhi + t * PX + 4 * kq) = hh;
                *reinterpret_cast<float4*>(Xlo + t * PX + 4 * kq) = ll;
            }
            __syncthreads();
        }
    }

    float* ob = out + ((size_t)b * TT + (size_t)s * CHUNK) * DD;
#pragma unroll
    for (int mt = 0; mt < 2; mt++)
#pragma unroll
        for (int nt = 0; nt < 8; nt++) {
            const int row = m0 + mt * 16 + gr;
            const int col = n0 + nt * 8 + 2 * gc;
            *reinterpret_cast<float2*>(ob + row * DD + col) =
                make_float2(acc[mt][nt][0], acc[mt][nt][1]);
            *reinterpret_cast<float2*>(ob + (row + 8) * DD + col) =
                make_float2(acc[mt][nt][2], acc[mt][nt][3]);
        }
}

// ---------------------------------------------------------------------------

extern "C" void kernel_launch(void* const* d_in, const int* in_sizes, int n_in,
                              void* d_out, int out_size)
{
    (void)in_sizes; (void)n_in; (void)out_size;
    const float* x = (const float*)d_in[0];
    float* out = (float*)d_out;

    const int smem1 = 2 * DD * P1 * 4;                    // 135168 B
    const int smem3 = 2 * DD * P1 * 4 + 2 * DD * PX * 4;  // 204800 B

    cudaFuncSetAttribute(syrk_kernel, cudaFuncAttributeMaxDynamicSharedMemorySize, smem1);
    cudaFuncSetAttribute(gemm_kernel, cudaFuncAttributeMaxDynamicSharedMemorySize, smem3);

    syrk_kernel<<<dim3(SPLITS, NB), 256, smem1>>>(x);
    reduce_kernel<<<64, 256>>>();
    gemm_kernel<<<dim3(SPLITS, NB), 256, smem3>>>(x, out);
}